// round 6
// baseline (speedup 1.0000x reference)
#include <cuda_runtime.h>
#include <cuda_fp16.h>
#include <mma.h>

// Problem constants (fixed by the dataset)
#define T_STEPS 8
#define N_NODES 50000
#define E_EDGES 800000
#define DD 64
#define NPART ((N_NODES + 255) / 256)   // 196 scan blocks

// -------- scratch (static __device__ arrays; no allocation allowed) --------
// y laid out [node][t][64]  -> node stride = 1024 B; 8 t-rows contiguous.
__device__ __half g_y[(size_t)N_NODES * T_STEPS * DD];   // 51.2 MB
__device__ int    g_offsets[N_NODES + 1];
__device__ int    g_cursor[N_NODES];
__device__ int2   g_edges[E_EDGES];     // (src | t_act<<20, w bits), CSR by dst

struct ScanState {
    int counts[N_NODES];
    int agg[NPART];
    int pre[NPART];
    int flag[NPART];     // 0=invalid, 1=aggregate ready, 2=prefix ready
};
__device__ ScanState g_ss;

// ---------------------------------------------------------------------------
// Kernel 1: count dst degrees, 4 edges/thread via int4
__global__ void count_kernel(const int* __restrict__ edge_index) {
    int i = blockIdx.x * blockDim.x + threadIdx.x;
    if (i >= E_EDGES / 4) return;
    int4 d = ((const int4*)(edge_index + E_EDGES))[i];
    atomicAdd(&g_ss.counts[d.x], 1);
    atomicAdd(&g_ss.counts[d.y], 1);
    atomicAdd(&g_ss.counts[d.z], 1);
    atomicAdd(&g_ss.counts[d.w], 1);
}

// ---------------------------------------------------------------------------
// Kernel 2: single-kernel decoupled-lookback exclusive scan -> offsets/cursor
__global__ __launch_bounds__(256) void scan_kernel() {
    __shared__ int wsum[8];
    __shared__ int base_s;
    int b = blockIdx.x, tid = threadIdx.x;
    int lane = tid & 31, wid = tid >> 5;
    int i = b * 256 + tid;
    int v = (i < N_NODES) ? g_ss.counts[i] : 0;

    int xi = v;
    #pragma unroll
    for (int o = 1; o < 32; o <<= 1) {
        int y = __shfl_up_sync(0xffffffffu, xi, o);
        if (lane >= o) xi += y;
    }
    if (lane == 31) wsum[wid] = xi;
    __syncthreads();
    if (tid == 0) {
        int a = 0;
        #pragma unroll
        for (int w = 0; w < 8; w++) { int t = wsum[w]; wsum[w] = a; a += t; }
    }
    __syncthreads();
    int excl = wsum[wid] + xi - v;

    if (tid == 255) {
        int total = excl + v;
        if (b == 0) {
            g_ss.pre[0] = total;
            __threadfence();
            atomicExch(&g_ss.flag[0], 2);
            base_s = 0;
        } else {
            g_ss.agg[b] = total;
            __threadfence();
            atomicExch(&g_ss.flag[b], 1);
            int base = 0;
            for (int j = b - 1; ; ) {
                int f;
                do { f = atomicAdd(&g_ss.flag[j], 0); } while (f == 0);
                if (f == 2) { base += atomicAdd(&g_ss.pre[j], 0); break; }
                base += atomicAdd(&g_ss.agg[j], 0);
                j--;
            }
            g_ss.pre[b] = base + total;
            __threadfence();
            atomicExch(&g_ss.flag[b], 2);
            base_s = base;
        }
        if (b == NPART - 1) g_offsets[N_NODES] = base_s + total;
    }
    __syncthreads();
    int off = base_s + excl;
    if (i < N_NODES) { g_offsets[i] = off; g_cursor[i] = off; }
}

// ---------------------------------------------------------------------------
// Kernel 3: place edges into CSR, 2 edges/thread for MLP
__device__ __forceinline__ void fill_one(int e, const int* edge_index,
                                         const float* edge_time,
                                         const float* node_time,
                                         const float* edge_weight) {
    int   src = edge_index[e];
    int   dst = edge_index[E_EDGES + e];
    float et  = edge_time[e];
    int tact = 0;
    #pragma unroll
    for (int t = 0; t < T_STEPS; t++) tact += (__ldg(&node_time[t]) < et) ? 1 : 0;
    int pos = atomicAdd(&g_cursor[dst], 1);
    g_edges[pos] = make_int2(src | (tact << 20), __float_as_int(edge_weight[e]));
}

__global__ void fill_kernel(const int* __restrict__ edge_index,
                            const float* __restrict__ edge_time,
                            const float* __restrict__ node_time,
                            const float* __restrict__ edge_weight) {
    int i = blockIdx.x * blockDim.x + threadIdx.x;
    if (i >= E_EDGES / 2) return;
    fill_one(i, edge_index, edge_time, node_time, edge_weight);
    fill_one(i + E_EDGES / 2, edge_index, edge_time, node_time, edge_weight);
}

// ---------------------------------------------------------------------------
// Kernel 4 (ncu-profiled slot): y = x @ W via wmma, transposed [N][T][64] out.
__global__ __launch_bounds__(256) void gemm_wmma_kernel(const float* __restrict__ x,
                                                        const float* __restrict__ W) {
    using namespace nvcuda;
    __shared__ __half xh[128 * 72];
    __shared__ __half Wh[64 * 72];
    int tid  = threadIdx.x;
    int warp = tid >> 5;
    size_t row0 = (size_t)blockIdx.x * 128;

    for (int i = tid; i < 64 * 16; i += 256) {
        int r = i >> 4, c = (i & 15) * 4;
        float4 v = ((const float4*)W)[i];
        __half2* p = (__half2*)(Wh + r * 72 + c);
        p[0] = __floats2half2_rn(v.x, v.y);
        p[1] = __floats2half2_rn(v.z, v.w);
    }
    for (int i = tid; i < 128 * 16; i += 256) {
        int r = i >> 4, c = (i & 15) * 4;
        float4 v = *(const float4*)(x + (row0 + r) * DD + c);
        __half2* p = (__half2*)(xh + r * 72 + c);
        p[0] = __floats2half2_rn(v.x, v.y);
        p[1] = __floats2half2_rn(v.z, v.w);
    }
    __syncthreads();

    wmma::fragment<wmma::accumulator, 16, 16, 16, float> acc[4];
    #pragma unroll
    for (int n = 0; n < 4; n++) wmma::fill_fragment(acc[n], 0.0f);

    #pragma unroll
    for (int k = 0; k < 4; k++) {
        wmma::fragment<wmma::matrix_a, 16, 16, 16, __half, wmma::row_major> af;
        wmma::load_matrix_sync(af, xh + (warp * 16) * 72 + k * 16, 72);
        #pragma unroll
        for (int n = 0; n < 4; n++) {
            wmma::fragment<wmma::matrix_b, 16, 16, 16, __half, wmma::row_major> bf;
            wmma::load_matrix_sync(bf, Wh + (k * 16) * 72 + n * 16, 72);
            wmma::mma_sync(acc[n], af, bf, acc[n]);
        }
    }

    // transposed store: input row r = t*N + node  ->  g_y[node*512 + t*64]
    int r = (int)row0 + warp * 16;
    int t = r / N_NODES;
    int node0 = r - t * N_NODES;
    __half* dst = g_y + (size_t)node0 * (T_STEPS * DD) + t * DD;
    #pragma unroll
    for (int n = 0; n < 4; n++) {
        wmma::fragment<wmma::accumulator, 16, 16, 16, __half> hacc;
        #pragma unroll
        for (int i = 0; i < hacc.num_elements; i++)
            hacc.x[i] = __float2half(acc[n].x[i]);
        wmma::store_matrix_sync(dst + n * 16, hacc, T_STEPS * DD, wmma::mem_row_major);
    }
}

// ---------------------------------------------------------------------------
// Kernel 5: gather. One warp per dst node; slot = lane>>3 (t-slot), cg = lane&7.
// tp0 (t=slot) guarded by a warp-UNIFORM branch (tact<4, ~50% skip);
// tp1 (t=4+slot) runs unconditionally with zero-masked weight.
// Loads are small-arm predicated (@p LDG.128, keeps MLP). fma.rn.f32x2 math.
__device__ __forceinline__ unsigned long long pack2(float a, float b) {
    unsigned long long r;
    asm("mov.b64 %0, {%1, %2};" : "=l"(r) : "f"(a), "f"(b));
    return r;
}
__device__ __forceinline__ float2 unpack2(unsigned long long v) {
    float2 f;
    asm("mov.b64 {%0, %1}, %2;" : "=f"(f.x), "=f"(f.y) : "l"(v));
    return f;
}
__device__ __forceinline__ void ffma2(unsigned long long& acc, unsigned long long v,
                                      unsigned long long w) {
    asm("fma.rn.f32x2 %0, %1, %2, %0;" : "+l"(acc) : "l"(v), "l"(w));
}
__device__ __forceinline__ void mac8(unsigned long long acc[4], uint4 h,
                                     unsigned long long w2) {
    float2 f0 = __half22float2(*(const __half2*)&h.x);
    float2 f1 = __half22float2(*(const __half2*)&h.y);
    float2 f2 = __half22float2(*(const __half2*)&h.z);
    float2 f3 = __half22float2(*(const __half2*)&h.w);
    ffma2(acc[0], pack2(f0.x, f0.y), w2);
    ffma2(acc[1], pack2(f1.x, f1.y), w2);
    ffma2(acc[2], pack2(f2.x, f2.y), w2);
    ffma2(acc[3], pack2(f3.x, f3.y), w2);
}

__global__ __launch_bounds__(128) void gather_kernel(const float* __restrict__ bias,
                                                     float* __restrict__ out) {
    int gwarp = (blockIdx.x * 128 + threadIdx.x) >> 5;
    int lane  = threadIdx.x & 31;
    if (gwarp >= N_NODES) return;
    int node = gwarp;
    int slot = lane >> 3;        // t-slot 0..3
    int cg   = lane & 7;         // column group (8 cols = 16 B)

    int off0 = g_offsets[node];
    int off1 = g_offsets[node + 1];

    unsigned long long acc0[4] = {0ull, 0ull, 0ull, 0ull};   // t = slot
    unsigned long long acc1[4] = {0ull, 0ull, 0ull, 0ull};   // t = 4 + slot
    const char* ybase = (const char*)g_y + slot * 128 + cg * 16;

    uint4 ha = {0,0,0,0}, hb = {0,0,0,0}, hc = {0,0,0,0}, hd = {0,0,0,0};

    int e = off0;
    for (; e + 1 < off1; e += 2) {
        int2 m0 = g_edges[e];
        int2 m1 = g_edges[e + 1];
        int ta0 = m0.x >> 20;
        int ta1 = m1.x >> 20;
        const char* p0 = ybase + ((size_t)(m0.x & 0xFFFFF) << 10);
        const char* p1 = ybase + ((size_t)(m1.x & 0xFFFFF) << 10);
        if (slot >= ta0)     ha = *(const uint4*)p0;
        if (slot + 4 >= ta0) hb = *(const uint4*)(p0 + 512);
        if (slot >= ta1)     hc = *(const uint4*)p1;
        if (slot + 4 >= ta1) hd = *(const uint4*)(p1 + 512);
        float w0 = __int_as_float(m0.y);
        float w1 = __int_as_float(m1.y);
        if (ta0 < 4) {                              // uniform branch, ~50% skip
            float wm = (slot >= ta0) ? w0 : 0.f;
            mac8(acc0, ha, pack2(wm, wm));
        }
        {                                            // unconditional, masked
            float wm = (slot + 4 >= ta0) ? w0 : 0.f;
            mac8(acc1, hb, pack2(wm, wm));
        }
        if (ta1 < 4) {
            float wm = (slot >= ta1) ? w1 : 0.f;
            mac8(acc0, hc, pack2(wm, wm));
        }
        {
            float wm = (slot + 4 >= ta1) ? w1 : 0.f;
            mac8(acc1, hd, pack2(wm, wm));
        }
    }
    if (e < off1) {
        int2 m0 = g_edges[e];
        int ta0 = m0.x >> 20;
        const char* p0 = ybase + ((size_t)(m0.x & 0xFFFFF) << 10);
        if (slot >= ta0)     ha = *(const uint4*)p0;
        if (slot + 4 >= ta0) hb = *(const uint4*)(p0 + 512);
        float w0 = __int_as_float(m0.y);
        if (ta0 < 4) {
            float wm = (slot >= ta0) ? w0 : 0.f;
            mac8(acc0, ha, pack2(wm, wm));
        }
        {
            float wm = (slot + 4 >= ta0) ? w0 : 0.f;
            mac8(acc1, hb, pack2(wm, wm));
        }
    }

    float4 b0 = *(const float4*)(bias + cg * 8);
    float4 b1 = *(const float4*)(bias + cg * 8 + 4);
    #pragma unroll
    for (int tp = 0; tp < 2; tp++) {
        const unsigned long long* a = (tp == 0) ? acc0 : acc1;
        float2 v0 = unpack2(a[0]);
        float2 v1 = unpack2(a[1]);
        float2 v2 = unpack2(a[2]);
        float2 v3 = unpack2(a[3]);
        int t = tp * 4 + slot;
        float* op = out + ((size_t)t * N_NODES + node) * DD + cg * 8;
        float4 o0, o1;
        o0.x = v0.x + b0.x; o0.y = v0.y + b0.y;
        o0.z = v1.x + b0.z; o0.w = v1.y + b0.w;
        o1.x = v2.x + b1.x; o1.y = v2.y + b1.y;
        o1.z = v3.x + b1.z; o1.w = v3.y + b1.w;
        *(float4*)op       = o0;
        *(float4*)(op + 4) = o1;
    }
}

// ---------------------------------------------------------------------------
extern "C" void kernel_launch(void* const* d_in, const int* in_sizes, int n_in,
                              void* d_out, int out_size) {
    const float* x           = (const float*)d_in[0];   // [T, N, 64]
    const int*   edge_index  = (const int*)  d_in[1];   // [2, E]
    const float* edge_time   = (const float*)d_in[2];   // [E]
    const float* node_time   = (const float*)d_in[3];   // [T]
    const float* edge_weight = (const float*)d_in[4];   // [E]
    const float* W           = (const float*)d_in[5];   // [64, 64]
    const float* bias        = (const float*)d_in[6];   // [64]
    float* out = (float*)d_out;                         // [T, N, 64]

    // zero counts + scan state in one memset (graph-capturable stream op)
    void* ss_ptr = nullptr;
    cudaGetSymbolAddress(&ss_ptr, g_ss);
    cudaMemsetAsync(ss_ptr, 0, sizeof(ScanState));

    // 1) degree count
    count_kernel<<<(E_EDGES / 4 + 255) / 256, 256>>>(edge_index);
    // 2) CSR offsets
    scan_kernel<<<NPART, 256>>>();
    // 3) CSR fill
    fill_kernel<<<(E_EDGES / 2 + 255) / 256, 256>>>(edge_index, edge_time, node_time, edge_weight);
    // 4) y = x @ W (tensor cores)  [4th kernel -> ncu profile slot]
    gemm_wmma_kernel<<<3125, 256>>>(x, W);
    // 5) gather
    gather_kernel<<<(N_NODES + 3) / 4, 128>>>(bias, out);
}

// round 7
// speedup vs baseline: 1.0775x; 1.0775x over previous
#include <cuda_runtime.h>
#include <cuda_fp16.h>
#include <mma.h>

// Problem constants (fixed by the dataset)
#define T_STEPS 8
#define N_NODES 50000
#define E_EDGES 800000
#define DD 64
#define TOTAL_ROWS (T_STEPS * N_NODES)    // 400000
#define NPART ((N_NODES + 255) / 256)     // 196 scan blocks

// -------- scratch (static __device__ arrays; no allocation allowed) --------
// y laid out [node][t][64]  -> node stride = 1024 B; 8 t-rows contiguous.
__device__ __half g_y[(size_t)N_NODES * T_STEPS * DD];   // 51.2 MB
__device__ int    g_offsets[N_NODES + 1];
__device__ int    g_cursor[N_NODES];
__device__ int2   g_edges[E_EDGES];     // (src | t_act<<20, w bits), CSR by dst

struct ScanState {
    int counts[N_NODES];
    int agg[NPART];
    int pre[NPART];
    int flag[NPART];     // 0=invalid, 1=aggregate ready, 2=prefix ready
};
__device__ ScanState g_ss;

// ---------------------------------------------------------------------------
// Kernel 1: y = x @ W via wmma, 256 rows/block (1563 blocks), FUSED dst-count.
// 16 float4 loads/thread (MLP 16) before the single barrier; each warp does
// two 16-row fragments (2x MMA per barrier). Output transposed [N][T][64].
__global__ __launch_bounds__(256) void gemm_count_kernel(const float* __restrict__ x,
                                                         const float* __restrict__ W,
                                                         const int* __restrict__ edge_index) {
    using namespace nvcuda;
    __shared__ __half xh[256 * 72];   // 36 KB
    __shared__ __half Wh[64 * 72];    //  9 KB
    int tid  = threadIdx.x;
    int warp = tid >> 5;
    int row0 = blockIdx.x * 256;

    // fused degree count: 2 edges per thread via int2 (1563*256 >= E/2)
    int ei = blockIdx.x * 256 + tid;
    if (ei < E_EDGES / 2) {
        int2 d = ((const int2*)(edge_index + E_EDGES))[ei];
        atomicAdd(&g_ss.counts[d.x], 1);
        atomicAdd(&g_ss.counts[d.y], 1);
    }

    // stage W (64x64) as half, stride 72 (conflict-free ldmatrix phases)
    for (int i = tid; i < 64 * 16; i += 256) {
        int r = i >> 4, c = (i & 15) * 4;
        float4 v = ((const float4*)W)[i];
        __half2* p = (__half2*)(Wh + r * 72 + c);
        p[0] = __floats2half2_rn(v.x, v.y);
        p[1] = __floats2half2_rn(v.z, v.w);
    }
    // stage x tile (256x64) as half: 16 float4 per thread, back-to-back issue
    #pragma unroll 4
    for (int i = tid; i < 256 * 16; i += 256) {
        int r = i >> 4, c = (i & 15) * 4;
        if (row0 + r < TOTAL_ROWS) {
            float4 v = *(const float4*)(x + (size_t)(row0 + r) * DD + c);
            __half2* p = (__half2*)(xh + r * 72 + c);
            p[0] = __floats2half2_rn(v.x, v.y);
            p[1] = __floats2half2_rn(v.z, v.w);
        }
    }
    __syncthreads();

    // each warp: rows [warp*32, warp*32+32) as two 16-row fragments
    #pragma unroll
    for (int h = 0; h < 2; h++) {
        int rloc = warp * 32 + h * 16;
        int r = row0 + rloc;
        if (r >= TOTAL_ROWS) break;

        wmma::fragment<wmma::accumulator, 16, 16, 16, float> acc[4];
        #pragma unroll
        for (int n = 0; n < 4; n++) wmma::fill_fragment(acc[n], 0.0f);

        #pragma unroll
        for (int k = 0; k < 4; k++) {
            wmma::fragment<wmma::matrix_a, 16, 16, 16, __half, wmma::row_major> af;
            wmma::load_matrix_sync(af, xh + rloc * 72 + k * 16, 72);
            #pragma unroll
            for (int n = 0; n < 4; n++) {
                wmma::fragment<wmma::matrix_b, 16, 16, 16, __half, wmma::row_major> bf;
                wmma::load_matrix_sync(bf, Wh + (k * 16) * 72 + n * 16, 72);
                wmma::mma_sync(acc[n], af, bf, acc[n]);
            }
        }

        // transposed store: input row r = t*N + node -> g_y[node*512 + t*64]
        // (50000 % 16 == 0 -> each 16-row fragment has uniform t)
        int t = r / N_NODES;
        int node0 = r - t * N_NODES;
        __half* dst = g_y + (size_t)node0 * (T_STEPS * DD) + t * DD;
        #pragma unroll
        for (int n = 0; n < 4; n++) {
            wmma::fragment<wmma::accumulator, 16, 16, 16, __half> hacc;
            #pragma unroll
            for (int i = 0; i < hacc.num_elements; i++)
                hacc.x[i] = __float2half(acc[n].x[i]);
            wmma::store_matrix_sync(dst + n * 16, hacc, T_STEPS * DD, wmma::mem_row_major);
        }
    }
}

// ---------------------------------------------------------------------------
// Kernel 2: single-kernel decoupled-lookback exclusive scan -> offsets/cursor
__global__ __launch_bounds__(256) void scan_kernel() {
    __shared__ int wsum[8];
    __shared__ int base_s;
    int b = blockIdx.x, tid = threadIdx.x;
    int lane = tid & 31, wid = tid >> 5;
    int i = b * 256 + tid;
    int v = (i < N_NODES) ? g_ss.counts[i] : 0;

    int xi = v;
    #pragma unroll
    for (int o = 1; o < 32; o <<= 1) {
        int y = __shfl_up_sync(0xffffffffu, xi, o);
        if (lane >= o) xi += y;
    }
    if (lane == 31) wsum[wid] = xi;
    __syncthreads();
    if (tid == 0) {
        int a = 0;
        #pragma unroll
        for (int w = 0; w < 8; w++) { int t = wsum[w]; wsum[w] = a; a += t; }
    }
    __syncthreads();
    int excl = wsum[wid] + xi - v;

    if (tid == 255) {
        int total = excl + v;
        if (b == 0) {
            g_ss.pre[0] = total;
            __threadfence();
            atomicExch(&g_ss.flag[0], 2);
            base_s = 0;
        } else {
            g_ss.agg[b] = total;
            __threadfence();
            atomicExch(&g_ss.flag[b], 1);
            int base = 0;
            for (int j = b - 1; ; ) {
                int f;
                do { f = atomicAdd(&g_ss.flag[j], 0); } while (f == 0);
                if (f == 2) { base += atomicAdd(&g_ss.pre[j], 0); break; }
                base += atomicAdd(&g_ss.agg[j], 0);
                j--;
            }
            g_ss.pre[b] = base + total;
            __threadfence();
            atomicExch(&g_ss.flag[b], 2);
            base_s = base;
        }
        if (b == NPART - 1) g_offsets[N_NODES] = base_s + total;
    }
    __syncthreads();
    int off = base_s + excl;
    if (i < N_NODES) { g_offsets[i] = off; g_cursor[i] = off; }
}

// ---------------------------------------------------------------------------
// Kernel 3: place edges into CSR, 2 edges/thread for MLP
__device__ __forceinline__ void fill_one(int e, const int* edge_index,
                                         const float* edge_time,
                                         const float* node_time,
                                         const float* edge_weight) {
    int   src = edge_index[e];
    int   dst = edge_index[E_EDGES + e];
    float et  = edge_time[e];
    int tact = 0;
    #pragma unroll
    for (int t = 0; t < T_STEPS; t++) tact += (__ldg(&node_time[t]) < et) ? 1 : 0;
    int pos = atomicAdd(&g_cursor[dst], 1);
    g_edges[pos] = make_int2(src | (tact << 20), __float_as_int(edge_weight[e]));
}

__global__ void fill_kernel(const int* __restrict__ edge_index,
                            const float* __restrict__ edge_time,
                            const float* __restrict__ node_time,
                            const float* __restrict__ edge_weight) {
    int i = blockIdx.x * blockDim.x + threadIdx.x;
    if (i >= E_EDGES / 2) return;
    fill_one(i, edge_index, edge_time, node_time, edge_weight);
    fill_one(i + E_EDGES / 2, edge_index, edge_time, node_time, edge_weight);
}

// ---------------------------------------------------------------------------
// Kernel 4 (ncu slot): gather. One warp per dst node; slot = lane>>3, cg = lane&7.
__device__ __forceinline__ unsigned long long pack2(float a, float b) {
    unsigned long long r;
    asm("mov.b64 %0, {%1, %2};" : "=l"(r) : "f"(a), "f"(b));
    return r;
}
__device__ __forceinline__ float2 unpack2(unsigned long long v) {
    float2 f;
    asm("mov.b64 {%0, %1}, %2;" : "=f"(f.x), "=f"(f.y) : "l"(v));
    return f;
}
__device__ __forceinline__ void ffma2(unsigned long long& acc, unsigned long long v,
                                      unsigned long long w) {
    asm("fma.rn.f32x2 %0, %1, %2, %0;" : "+l"(acc) : "l"(v), "l"(w));
}
__device__ __forceinline__ void mac8(unsigned long long acc[4], uint4 h,
                                     unsigned long long w2) {
    float2 f0 = __half22float2(*(const __half2*)&h.x);
    float2 f1 = __half22float2(*(const __half2*)&h.y);
    float2 f2 = __half22float2(*(const __half2*)&h.z);
    float2 f3 = __half22float2(*(const __half2*)&h.w);
    ffma2(acc[0], pack2(f0.x, f0.y), w2);
    ffma2(acc[1], pack2(f1.x, f1.y), w2);
    ffma2(acc[2], pack2(f2.x, f2.y), w2);
    ffma2(acc[3], pack2(f3.x, f3.y), w2);
}

__global__ __launch_bounds__(128) void gather_kernel(const float* __restrict__ bias,
                                                     float* __restrict__ out) {
    int gwarp = (blockIdx.x * 128 + threadIdx.x) >> 5;
    int lane  = threadIdx.x & 31;
    if (gwarp >= N_NODES) return;
    int node = gwarp;
    int slot = lane >> 3;        // t-slot 0..3
    int cg   = lane & 7;         // column group (8 cols = 16 B)

    int off0 = g_offsets[node];
    int off1 = g_offsets[node + 1];

    unsigned long long acc0[4] = {0ull, 0ull, 0ull, 0ull};   // t = slot
    unsigned long long acc1[4] = {0ull, 0ull, 0ull, 0ull};   // t = 4 + slot
    const char* ybase = (const char*)g_y + slot * 128 + cg * 16;

    uint4 ha = {0,0,0,0}, hb = {0,0,0,0}, hc = {0,0,0,0}, hd = {0,0,0,0};

    int e = off0;
    for (; e + 1 < off1; e += 2) {
        int2 m0 = g_edges[e];
        int2 m1 = g_edges[e + 1];
        int ta0 = m0.x >> 20;
        int ta1 = m1.x >> 20;
        const char* p0 = ybase + ((size_t)(m0.x & 0xFFFFF) << 10);
        const char* p1 = ybase + ((size_t)(m1.x & 0xFFFFF) << 10);
        if (slot >= ta0)     ha = *(const uint4*)p0;
        if (slot + 4 >= ta0) hb = *(const uint4*)(p0 + 512);
        if (slot >= ta1)     hc = *(const uint4*)p1;
        if (slot + 4 >= ta1) hd = *(const uint4*)(p1 + 512);
        float w0 = __int_as_float(m0.y);
        float w1 = __int_as_float(m1.y);
        if (ta0 < 4) {                              // uniform branch, ~50% skip
            float wm = (slot >= ta0) ? w0 : 0.f;
            mac8(acc0, ha, pack2(wm, wm));
        }
        {                                            // unconditional, masked
            float wm = (slot + 4 >= ta0) ? w0 : 0.f;
            mac8(acc1, hb, pack2(wm, wm));
        }
        if (ta1 < 4) {
            float wm = (slot >= ta1) ? w1 : 0.f;
            mac8(acc0, hc, pack2(wm, wm));
        }
        {
            float wm = (slot + 4 >= ta1) ? w1 : 0.f;
            mac8(acc1, hd, pack2(wm, wm));
        }
    }
    if (e < off1) {
        int2 m0 = g_edges[e];
        int ta0 = m0.x >> 20;
        const char* p0 = ybase + ((size_t)(m0.x & 0xFFFFF) << 10);
        if (slot >= ta0)     ha = *(const uint4*)p0;
        if (slot + 4 >= ta0) hb = *(const uint4*)(p0 + 512);
        float w0 = __int_as_float(m0.y);
        if (ta0 < 4) {
            float wm = (slot >= ta0) ? w0 : 0.f;
            mac8(acc0, ha, pack2(wm, wm));
        }
        {
            float wm = (slot + 4 >= ta0) ? w0 : 0.f;
            mac8(acc1, hb, pack2(wm, wm));
        }
    }

    float4 b0 = *(const float4*)(bias + cg * 8);
    float4 b1 = *(const float4*)(bias + cg * 8 + 4);
    #pragma unroll
    for (int tp = 0; tp < 2; tp++) {
        const unsigned long long* a = (tp == 0) ? acc0 : acc1;
        float2 v0 = unpack2(a[0]);
        float2 v1 = unpack2(a[1]);
        float2 v2 = unpack2(a[2]);
        float2 v3 = unpack2(a[3]);
        int t = tp * 4 + slot;
        float* op = out + ((size_t)t * N_NODES + node) * DD + cg * 8;
        float4 o0, o1;
        o0.x = v0.x + b0.x; o0.y = v0.y + b0.y;
        o0.z = v1.x + b0.z; o0.w = v1.y + b0.w;
        o1.x = v2.x + b1.x; o1.y = v2.y + b1.y;
        o1.z = v3.x + b1.z; o1.w = v3.y + b1.w;
        *(float4*)op       = o0;
        *(float4*)(op + 4) = o1;
    }
}

// ---------------------------------------------------------------------------
extern "C" void kernel_launch(void* const* d_in, const int* in_sizes, int n_in,
                              void* d_out, int out_size) {
    const float* x           = (const float*)d_in[0];   // [T, N, 64]
    const int*   edge_index  = (const int*)  d_in[1];   // [2, E]
    const float* edge_time   = (const float*)d_in[2];   // [E]
    const float* node_time   = (const float*)d_in[3];   // [T]
    const float* edge_weight = (const float*)d_in[4];   // [E]
    const float* W           = (const float*)d_in[5];   // [64, 64]
    const float* bias        = (const float*)d_in[6];   // [64]
    float* out = (float*)d_out;                         // [T, N, 64]

    // zero counts + scan state in one memset (graph-capturable stream op)
    void* ss_ptr = nullptr;
    cudaGetSymbolAddress(&ss_ptr, g_ss);
    cudaMemsetAsync(ss_ptr, 0, sizeof(ScanState));

    // 1) y = x @ W (256 rows/block) + fused degree count
    gemm_count_kernel<<<(TOTAL_ROWS + 255) / 256, 256>>>(x, W, edge_index);
    // 2) CSR offsets
    scan_kernel<<<NPART, 256>>>();
    // 3) CSR fill
    fill_kernel<<<(E_EDGES / 2 + 255) / 256, 256>>>(edge_index, edge_time, node_time, edge_weight);
    // 4) gather  [4th kernel -> ncu profile slot]
    gather_kernel<<<(N_NODES + 3) / 4, 128>>>(bias, out);
}

// round 8
// speedup vs baseline: 1.1804x; 1.0954x over previous
#include <cuda_runtime.h>
#include <cuda_fp16.h>
#include <mma.h>

// Problem constants (fixed by the dataset)
#define T_STEPS 8
#define N_NODES 50000
#define E_EDGES 800000
#define DD 64
#define TOTAL_ROWS (T_STEPS * N_NODES)    // 400000
#define NPART ((N_NODES + 255) / 256)     // 196 scan blocks

// -------- scratch (static __device__ arrays; no allocation allowed) --------
// y laid out [node][t][64]  -> node stride = 1024 B; 8 t-rows contiguous.
__device__ __half g_y[(size_t)N_NODES * T_STEPS * DD];   // 51.2 MB
__device__ int    g_offsets[N_NODES + 1];
__device__ int    g_mid[N_NODES];       // off + #(tact<4)
__device__ int    g_curA[N_NODES];      // cursor for tact<4 region
__device__ int    g_curB[N_NODES];      // cursor for 4<=tact<8 region
__device__ int2   g_edges[E_EDGES];     // ((src<<10)|tact, w bits); dead edges dropped

struct ScanState {
    int counts[N_NODES];   // #(tact<8) per dst
    int cntA[N_NODES];     // #(tact<4) per dst
    int agg[NPART];
    int pre[NPART];
    int flag[NPART];       // 0=invalid, 1=aggregate ready, 2=prefix ready
};
__device__ ScanState g_ss;

// ---------------------------------------------------------------------------
__device__ __forceinline__ int compute_tact(float et, const float* __restrict__ node_time) {
    int tact = 0;
    #pragma unroll
    for (int t = 0; t < T_STEPS; t++) tact += (__ldg(&node_time[t]) < et) ? 1 : 0;
    return tact;
}

// ---------------------------------------------------------------------------
// Kernel 1: y = x @ W via wmma, 256 rows/block (1563 blocks).
// FUSED: each thread counts 2 edges (total if tact<8, cntA if tact<4); the
// atomics + tact math hide in the GEMM's memory-latency slack.
__global__ __launch_bounds__(256) void gemm_count_kernel(const float* __restrict__ x,
                                                         const float* __restrict__ W,
                                                         const int* __restrict__ edge_index,
                                                         const float* __restrict__ edge_time,
                                                         const float* __restrict__ node_time) {
    using namespace nvcuda;
    __shared__ __half xh[256 * 72];   // 36 KB
    __shared__ __half Wh[64 * 72];    //  9 KB
    int tid  = threadIdx.x;
    int warp = tid >> 5;
    int row0 = blockIdx.x * 256;

    // fused degree count: 2 edges per thread
    int ei = blockIdx.x * 256 + tid;
    if (ei < E_EDGES / 2) {
        int2   d  = ((const int2*)(edge_index + E_EDGES))[ei];
        float2 et = ((const float2*)edge_time)[ei];
        int ta0 = compute_tact(et.x, node_time);
        int ta1 = compute_tact(et.y, node_time);
        if (ta0 < 8) atomicAdd(&g_ss.counts[d.x], 1);
        if (ta0 < 4) atomicAdd(&g_ss.cntA[d.x], 1);
        if (ta1 < 8) atomicAdd(&g_ss.counts[d.y], 1);
        if (ta1 < 4) atomicAdd(&g_ss.cntA[d.y], 1);
    }

    // stage W (64x64) as half, stride 72 (conflict-free ldmatrix phases)
    for (int i = tid; i < 64 * 16; i += 256) {
        int r = i >> 4, c = (i & 15) * 4;
        float4 v = ((const float4*)W)[i];
        __half2* p = (__half2*)(Wh + r * 72 + c);
        p[0] = __floats2half2_rn(v.x, v.y);
        p[1] = __floats2half2_rn(v.z, v.w);
    }
    // stage x tile (256x64) as half: 16 float4/thread, back-to-back issue
    #pragma unroll 4
    for (int i = tid; i < 256 * 16; i += 256) {
        int r = i >> 4, c = (i & 15) * 4;
        if (row0 + r < TOTAL_ROWS) {
            float4 v = *(const float4*)(x + (size_t)(row0 + r) * DD + c);
            __half2* p = (__half2*)(xh + r * 72 + c);
            p[0] = __floats2half2_rn(v.x, v.y);
            p[1] = __floats2half2_rn(v.z, v.w);
        }
    }
    __syncthreads();

    #pragma unroll
    for (int h = 0; h < 2; h++) {
        int rloc = warp * 32 + h * 16;
        int r = row0 + rloc;
        if (r >= TOTAL_ROWS) break;

        wmma::fragment<wmma::accumulator, 16, 16, 16, float> acc[4];
        #pragma unroll
        for (int n = 0; n < 4; n++) wmma::fill_fragment(acc[n], 0.0f);

        #pragma unroll
        for (int k = 0; k < 4; k++) {
            wmma::fragment<wmma::matrix_a, 16, 16, 16, __half, wmma::row_major> af;
            wmma::load_matrix_sync(af, xh + rloc * 72 + k * 16, 72);
            #pragma unroll
            for (int n = 0; n < 4; n++) {
                wmma::fragment<wmma::matrix_b, 16, 16, 16, __half, wmma::row_major> bf;
                wmma::load_matrix_sync(bf, Wh + (k * 16) * 72 + n * 16, 72);
                wmma::mma_sync(acc[n], af, bf, acc[n]);
            }
        }

        // transposed store: input row r = t*N + node -> g_y[node*512 + t*64]
        int t = r / N_NODES;
        int node0 = r - t * N_NODES;
        __half* dst = g_y + (size_t)node0 * (T_STEPS * DD) + t * DD;
        #pragma unroll
        for (int n = 0; n < 4; n++) {
            wmma::fragment<wmma::accumulator, 16, 16, 16, __half> hacc;
            #pragma unroll
            for (int i = 0; i < hacc.num_elements; i++)
                hacc.x[i] = __float2half(acc[n].x[i]);
            wmma::store_matrix_sync(dst + n * 16, hacc, T_STEPS * DD, wmma::mem_row_major);
        }
    }
}

// ---------------------------------------------------------------------------
// Kernel 2: decoupled-lookback exclusive scan over counts -> offsets; also
// emits mid = off + cntA and initializes both region cursors.
__global__ __launch_bounds__(256) void scan_kernel() {
    __shared__ int wsum[8];
    __shared__ int base_s;
    int b = blockIdx.x, tid = threadIdx.x;
    int lane = tid & 31, wid = tid >> 5;
    int i = b * 256 + tid;
    int v = (i < N_NODES) ? g_ss.counts[i] : 0;

    int xi = v;
    #pragma unroll
    for (int o = 1; o < 32; o <<= 1) {
        int y = __shfl_up_sync(0xffffffffu, xi, o);
        if (lane >= o) xi += y;
    }
    if (lane == 31) wsum[wid] = xi;
    __syncthreads();
    if (tid == 0) {
        int a = 0;
        #pragma unroll
        for (int w = 0; w < 8; w++) { int t = wsum[w]; wsum[w] = a; a += t; }
    }
    __syncthreads();
    int excl = wsum[wid] + xi - v;

    if (tid == 255) {
        int total = excl + v;
        if (b == 0) {
            g_ss.pre[0] = total;
            __threadfence();
            atomicExch(&g_ss.flag[0], 2);
            base_s = 0;
        } else {
            g_ss.agg[b] = total;
            __threadfence();
            atomicExch(&g_ss.flag[b], 1);
            int base = 0;
            for (int j = b - 1; ; ) {
                int f;
                do { f = atomicAdd(&g_ss.flag[j], 0); } while (f == 0);
                if (f == 2) { base += atomicAdd(&g_ss.pre[j], 0); break; }
                base += atomicAdd(&g_ss.agg[j], 0);
                j--;
            }
            g_ss.pre[b] = base + total;
            __threadfence();
            atomicExch(&g_ss.flag[b], 2);
            base_s = base;
        }
        if (b == NPART - 1) g_offsets[N_NODES] = base_s + total;
    }
    __syncthreads();
    if (i < N_NODES) {
        int off = base_s + excl;
        int mid = off + g_ss.cntA[i];
        g_offsets[i] = off;
        g_mid[i]     = mid;
        g_curA[i]    = off;
        g_curB[i]    = mid;
    }
}

// ---------------------------------------------------------------------------
// Kernel 3: place live edges into partitioned CSR; dead (tact==8) dropped.
// Packed word = (src<<10) | tact  (node stride in g_y is 1024 B).
__device__ __forceinline__ void fill_one(int e, const int* edge_index,
                                         const float* edge_time,
                                         const float* node_time,
                                         const float* edge_weight) {
    int   src = edge_index[e];
    int   dst = edge_index[E_EDGES + e];
    int  tact = compute_tact(edge_time[e], node_time);
    if (tact >= 8) return;
    int* cur = (tact < 4) ? &g_curA[dst] : &g_curB[dst];
    int pos = atomicAdd(cur, 1);
    g_edges[pos] = make_int2((src << 10) | tact, __float_as_int(edge_weight[e]));
}

__global__ void fill_kernel(const int* __restrict__ edge_index,
                            const float* __restrict__ edge_time,
                            const float* __restrict__ node_time,
                            const float* __restrict__ edge_weight) {
    int i = blockIdx.x * blockDim.x + threadIdx.x;
    if (i >= E_EDGES / 2) return;
    fill_one(i, edge_index, edge_time, node_time, edge_weight);
    fill_one(i + E_EDGES / 2, edge_index, edge_time, node_time, edge_weight);
}

// ---------------------------------------------------------------------------
// Kernel 4 (ncu slot): gather. TWO warps per dst node:
//   group0 (t=0..3) iterates [off, mid)   — only tact<4 edges
//   group1 (t=4..7) iterates [off, off1)  — all live edges
// Lane: slot = lane>>3 -> t = group*4+slot; cg = lane&7 -> 8 cols (16 B).
__device__ __forceinline__ unsigned long long pack2(float a, float b) {
    unsigned long long r;
    asm("mov.b64 %0, {%1, %2};" : "=l"(r) : "f"(a), "f"(b));
    return r;
}
__device__ __forceinline__ float2 unpack2(unsigned long long v) {
    float2 f;
    asm("mov.b64 {%0, %1}, %2;" : "=f"(f.x), "=f"(f.y) : "l"(v));
    return f;
}
__device__ __forceinline__ void ffma2(unsigned long long& acc, unsigned long long v,
                                      unsigned long long w) {
    asm("fma.rn.f32x2 %0, %1, %2, %0;" : "+l"(acc) : "l"(v), "l"(w));
}
__device__ __forceinline__ void mac8(unsigned long long acc[4], uint4 h,
                                     unsigned long long w2) {
    float2 f0 = __half22float2(*(const __half2*)&h.x);
    float2 f1 = __half22float2(*(const __half2*)&h.y);
    float2 f2 = __half22float2(*(const __half2*)&h.z);
    float2 f3 = __half22float2(*(const __half2*)&h.w);
    ffma2(acc[0], pack2(f0.x, f0.y), w2);
    ffma2(acc[1], pack2(f1.x, f1.y), w2);
    ffma2(acc[2], pack2(f2.x, f2.y), w2);
    ffma2(acc[3], pack2(f3.x, f3.y), w2);
}

__global__ __launch_bounds__(128) void gather_kernel(const float* __restrict__ bias,
                                                     float* __restrict__ out) {
    int gw   = (blockIdx.x * 128 + threadIdx.x) >> 5;
    int lane = threadIdx.x & 31;
    if (gw >= 2 * N_NODES) return;
    int node  = gw >> 1;
    int group = gw & 1;
    int slot  = lane >> 3;          // 0..3
    int cg    = lane & 7;           // column group (16 B)
    int t     = group * 4 + slot;

    int e  = g_offsets[node];
    int e1 = group ? g_offsets[node + 1] : g_mid[node];

    unsigned long long acc[4] = {0ull, 0ull, 0ull, 0ull};
    const char* ybase = (const char*)g_y + t * 128 + cg * 16;

    uint4 h0 = {0,0,0,0}, h1 = {0,0,0,0};

    for (; e + 1 < e1; e += 2) {
        int2 m0 = g_edges[e];
        int2 m1 = g_edges[e + 1];
        const char* p0 = ybase + (size_t)(unsigned)(m0.x & 0xFFFFFC00);
        const char* p1 = ybase + (size_t)(unsigned)(m1.x & 0xFFFFFC00);
        int ta0 = m0.x & 15;
        int ta1 = m1.x & 15;
        bool a0 = (t >= ta0);
        bool a1 = (t >= ta1);
        if (a0) h0 = *(const uint4*)p0;
        if (a1) h1 = *(const uint4*)p1;
        float w0 = a0 ? __int_as_float(m0.y) : 0.f;
        float w1 = a1 ? __int_as_float(m1.y) : 0.f;
        mac8(acc, h0, pack2(w0, w0));
        mac8(acc, h1, pack2(w1, w1));
    }
    if (e < e1) {
        int2 m0 = g_edges[e];
        const char* p0 = ybase + (size_t)(unsigned)(m0.x & 0xFFFFFC00);
        int ta0 = m0.x & 15;
        bool a0 = (t >= ta0);
        if (a0) h0 = *(const uint4*)p0;
        float w0 = a0 ? __int_as_float(m0.y) : 0.f;
        mac8(acc, h0, pack2(w0, w0));
    }

    float4 b0 = *(const float4*)(bias + cg * 8);
    float4 b1 = *(const float4*)(bias + cg * 8 + 4);
    float2 v0 = unpack2(acc[0]);
    float2 v1 = unpack2(acc[1]);
    float2 v2 = unpack2(acc[2]);
    float2 v3 = unpack2(acc[3]);
    float* op = out + ((size_t)t * N_NODES + node) * DD + cg * 8;
    float4 o0, o1;
    o0.x = v0.x + b0.x; o0.y = v0.y + b0.y;
    o0.z = v1.x + b0.z; o0.w = v1.y + b0.w;
    o1.x = v2.x + b1.x; o1.y = v2.y + b1.y;
    o1.z = v3.x + b1.z; o1.w = v3.y + b1.w;
    *(float4*)op       = o0;
    *(float4*)(op + 4) = o1;
}

// ---------------------------------------------------------------------------
extern "C" void kernel_launch(void* const* d_in, const int* in_sizes, int n_in,
                              void* d_out, int out_size) {
    const float* x           = (const float*)d_in[0];   // [T, N, 64]
    const int*   edge_index  = (const int*)  d_in[1];   // [2, E]
    const float* edge_time   = (const float*)d_in[2];   // [E]
    const float* node_time   = (const float*)d_in[3];   // [T]
    const float* edge_weight = (const float*)d_in[4];   // [E]
    const float* W           = (const float*)d_in[5];   // [64, 64]
    const float* bias        = (const float*)d_in[6];   // [64]
    float* out = (float*)d_out;                         // [T, N, 64]

    // zero counts/cntA + scan state in one memset (graph-capturable stream op)
    void* ss_ptr = nullptr;
    cudaGetSymbolAddress(&ss_ptr, g_ss);
    cudaMemsetAsync(ss_ptr, 0, sizeof(ScanState));

    // 1) y = x @ W (256 rows/block) + fused partitioned degree count
    gemm_count_kernel<<<(TOTAL_ROWS + 255) / 256, 256>>>(x, W, edge_index, edge_time, node_time);
    // 2) CSR offsets + mid + cursors
    scan_kernel<<<NPART, 256>>>();
    // 3) partitioned CSR fill (dead edges dropped)
    fill_kernel<<<(E_EDGES / 2 + 255) / 256, 256>>>(edge_index, edge_time, node_time, edge_weight);
    // 4) gather  [4th kernel -> ncu profile slot]
    gather_kernel<<<(2 * N_NODES + 3) / 4, 128>>>(bias, out);
}

// round 9
// speedup vs baseline: 1.2347x; 1.0460x over previous
#include <cuda_runtime.h>
#include <cuda_fp16.h>
#include <mma.h>

// Problem constants (fixed by the dataset)
#define T_STEPS 8
#define N_NODES 50000
#define E_EDGES 800000
#define DD 64
#define TOTAL_ROWS (T_STEPS * N_NODES)    // 400000
#define NPART ((N_NODES + 255) / 256)     // 196 scan blocks

// -------- scratch (static __device__ arrays; no allocation allowed) --------
// y laid out [node][t][64]  -> node stride = 1024 B; 8 t-rows contiguous.
__device__ __half g_y[(size_t)N_NODES * T_STEPS * DD];   // 51.2 MB
__device__ int    g_offsets[N_NODES + 1];
__device__ int    g_mid[N_NODES];       // off + #(tact<4)
__device__ int    g_curA[N_NODES];      // cursor for tact<4 region
__device__ int    g_curB[N_NODES];      // cursor for 4<=tact<8 region
__device__ int2   g_edges[E_EDGES];     // ((src<<10)|tact, w bits); dead edges dropped

struct ScanState {
    int counts[N_NODES];   // #(tact<8) per dst   (re-zeroed by gather_kernel)
    int cntA[N_NODES];     // #(tact<4) per dst   (re-zeroed by gather_kernel)
    int agg[NPART];
    int pre[NPART];
    int flag[NPART];       // 0=invalid, 1=aggregate, 2=prefix (re-zeroed by gather)
};
__device__ ScanState g_ss;

// ---------------------------------------------------------------------------
__device__ __forceinline__ int compute_tact(float et, const float* __restrict__ node_time) {
    int tact = 0;
    #pragma unroll
    for (int t = 0; t < T_STEPS; t++) tact += (__ldg(&node_time[t]) < et) ? 1 : 0;
    return tact;
}

// ---------------------------------------------------------------------------
// Kernel 1: y = x @ W via wmma, 256 rows/block (1563 blocks), fused counts.
__global__ __launch_bounds__(256) void gemm_count_kernel(const float* __restrict__ x,
                                                         const float* __restrict__ W,
                                                         const int* __restrict__ edge_index,
                                                         const float* __restrict__ edge_time,
                                                         const float* __restrict__ node_time) {
    using namespace nvcuda;
    __shared__ __half xh[256 * 72];   // 36 KB
    __shared__ __half Wh[64 * 72];    //  9 KB
    int tid  = threadIdx.x;
    int warp = tid >> 5;
    int row0 = blockIdx.x * 256;

    // stage x tile first (16 float4/thread, front-batched for MLP)
    #pragma unroll 8
    for (int i = tid; i < 256 * 16; i += 256) {
        int r = i >> 4, c = (i & 15) * 4;
        if (row0 + r < TOTAL_ROWS) {
            float4 v = *(const float4*)(x + (size_t)(row0 + r) * DD + c);
            __half2* p = (__half2*)(xh + r * 72 + c);
            p[0] = __floats2half2_rn(v.x, v.y);
            p[1] = __floats2half2_rn(v.z, v.w);
        }
    }
    // stage W (64x64) as half, stride 72
    #pragma unroll
    for (int i = tid; i < 64 * 16; i += 256) {
        int r = i >> 4, c = (i & 15) * 4;
        float4 v = ((const float4*)W)[i];
        __half2* p = (__half2*)(Wh + r * 72 + c);
        p[0] = __floats2half2_rn(v.x, v.y);
        p[1] = __floats2half2_rn(v.z, v.w);
    }
    // fused partitioned degree count: 2 edges/thread (hides in load slack)
    int ei = blockIdx.x * 256 + tid;
    if (ei < E_EDGES / 2) {
        int2   d  = ((const int2*)(edge_index + E_EDGES))[ei];
        float2 et = ((const float2*)edge_time)[ei];
        int ta0 = compute_tact(et.x, node_time);
        int ta1 = compute_tact(et.y, node_time);
        if (ta0 < 8) atomicAdd(&g_ss.counts[d.x], 1);
        if (ta0 < 4) atomicAdd(&g_ss.cntA[d.x], 1);
        if (ta1 < 8) atomicAdd(&g_ss.counts[d.y], 1);
        if (ta1 < 4) atomicAdd(&g_ss.cntA[d.y], 1);
    }
    __syncthreads();

    #pragma unroll
    for (int h = 0; h < 2; h++) {
        int rloc = warp * 32 + h * 16;
        int r = row0 + rloc;
        if (r >= TOTAL_ROWS) break;

        wmma::fragment<wmma::accumulator, 16, 16, 16, float> acc[4];
        #pragma unroll
        for (int n = 0; n < 4; n++) wmma::fill_fragment(acc[n], 0.0f);

        #pragma unroll
        for (int k = 0; k < 4; k++) {
            wmma::fragment<wmma::matrix_a, 16, 16, 16, __half, wmma::row_major> af;
            wmma::load_matrix_sync(af, xh + rloc * 72 + k * 16, 72);
            #pragma unroll
            for (int n = 0; n < 4; n++) {
                wmma::fragment<wmma::matrix_b, 16, 16, 16, __half, wmma::row_major> bf;
                wmma::load_matrix_sync(bf, Wh + (k * 16) * 72 + n * 16, 72);
                wmma::mma_sync(acc[n], af, bf, acc[n]);
            }
        }

        // transposed store: input row r = t*N + node -> g_y[node*512 + t*64]
        int t = r / N_NODES;
        int node0 = r - t * N_NODES;
        __half* dst = g_y + (size_t)node0 * (T_STEPS * DD) + t * DD;
        #pragma unroll
        for (int n = 0; n < 4; n++) {
            wmma::fragment<wmma::accumulator, 16, 16, 16, __half> hacc;
            #pragma unroll
            for (int i = 0; i < hacc.num_elements; i++)
                hacc.x[i] = __float2half(acc[n].x[i]);
            wmma::store_matrix_sync(dst + n * 16, hacc, T_STEPS * DD, wmma::mem_row_major);
        }
    }
}

// ---------------------------------------------------------------------------
// Kernel 2: decoupled-lookback exclusive scan -> offsets, mid, cursors
__global__ __launch_bounds__(256) void scan_kernel() {
    __shared__ int wsum[8];
    __shared__ int base_s;
    int b = blockIdx.x, tid = threadIdx.x;
    int lane = tid & 31, wid = tid >> 5;
    int i = b * 256 + tid;
    int v = (i < N_NODES) ? g_ss.counts[i] : 0;

    int xi = v;
    #pragma unroll
    for (int o = 1; o < 32; o <<= 1) {
        int y = __shfl_up_sync(0xffffffffu, xi, o);
        if (lane >= o) xi += y;
    }
    if (lane == 31) wsum[wid] = xi;
    __syncthreads();
    if (tid == 0) {
        int a = 0;
        #pragma unroll
        for (int w = 0; w < 8; w++) { int t = wsum[w]; wsum[w] = a; a += t; }
    }
    __syncthreads();
    int excl = wsum[wid] + xi - v;

    if (tid == 255) {
        int total = excl + v;
        if (b == 0) {
            g_ss.pre[0] = total;
            __threadfence();
            atomicExch(&g_ss.flag[0], 2);
            base_s = 0;
        } else {
            g_ss.agg[b] = total;
            __threadfence();
            atomicExch(&g_ss.flag[b], 1);
            int base = 0;
            for (int j = b - 1; ; ) {
                int f;
                do { f = atomicAdd(&g_ss.flag[j], 0); } while (f == 0);
                if (f == 2) { base += atomicAdd(&g_ss.pre[j], 0); break; }
                base += atomicAdd(&g_ss.agg[j], 0);
                j--;
            }
            g_ss.pre[b] = base + total;
            __threadfence();
            atomicExch(&g_ss.flag[b], 2);
            base_s = base;
        }
        if (b == NPART - 1) g_offsets[N_NODES] = base_s + total;
    }
    __syncthreads();
    if (i < N_NODES) {
        int off = base_s + excl;
        int mid = off + g_ss.cntA[i];
        g_offsets[i] = off;
        g_mid[i]     = mid;
        g_curA[i]    = off;
        g_curB[i]    = mid;
    }
}

// ---------------------------------------------------------------------------
// Kernel 3: partitioned CSR fill; dead (tact==8) edges dropped.
__device__ __forceinline__ void fill_one(int e, const int* edge_index,
                                         const float* edge_time,
                                         const float* node_time,
                                         const float* edge_weight) {
    int   src = edge_index[e];
    int   dst = edge_index[E_EDGES + e];
    int  tact = compute_tact(edge_time[e], node_time);
    if (tact >= 8) return;
    int* cur = (tact < 4) ? &g_curA[dst] : &g_curB[dst];
    int pos = atomicAdd(cur, 1);
    g_edges[pos] = make_int2((src << 10) | tact, __float_as_int(edge_weight[e]));
}

__global__ void fill_kernel(const int* __restrict__ edge_index,
                            const float* __restrict__ edge_time,
                            const float* __restrict__ node_time,
                            const float* __restrict__ edge_weight) {
    int i = blockIdx.x * blockDim.x + threadIdx.x;
    if (i >= E_EDGES / 2) return;
    fill_one(i, edge_index, edge_time, node_time, edge_weight);
    fill_one(i + E_EDGES / 2, edge_index, edge_time, node_time, edge_weight);
}

// ---------------------------------------------------------------------------
// Kernel 4: gather. TWO warps per dst node.
//  group0 (t=0..3): predicated loop over region A [off, mid)
//  group1 (t=4..7): UNCONDITIONAL x4 loop over region A (always active for
//                   t>=4: no predicates, no selects) + predicated [mid, off1)
__device__ __forceinline__ unsigned long long pack2(float a, float b) {
    unsigned long long r;
    asm("mov.b64 %0, {%1, %2};" : "=l"(r) : "f"(a), "f"(b));
    return r;
}
__device__ __forceinline__ float2 unpack2(unsigned long long v) {
    float2 f;
    asm("mov.b64 {%0, %1}, %2;" : "=f"(f.x), "=f"(f.y) : "l"(v));
    return f;
}
__device__ __forceinline__ void ffma2(unsigned long long& acc, unsigned long long v,
                                      unsigned long long w) {
    asm("fma.rn.f32x2 %0, %1, %2, %0;" : "+l"(acc) : "l"(v), "l"(w));
}
__device__ __forceinline__ void mac8(unsigned long long acc[4], uint4 h, float w) {
    unsigned long long w2 = pack2(w, w);
    float2 f0 = __half22float2(*(const __half2*)&h.x);
    float2 f1 = __half22float2(*(const __half2*)&h.y);
    float2 f2 = __half22float2(*(const __half2*)&h.z);
    float2 f3 = __half22float2(*(const __half2*)&h.w);
    ffma2(acc[0], pack2(f0.x, f0.y), w2);
    ffma2(acc[1], pack2(f1.x, f1.y), w2);
    ffma2(acc[2], pack2(f2.x, f2.y), w2);
    ffma2(acc[3], pack2(f3.x, f3.y), w2);
}

// predicated pass over [e, e1): active iff t >= (m.x & 15)
__device__ __forceinline__ int gather_pred(int e, int e1, int t, const char* ybase,
                                           unsigned long long acc[4]) {
    uint4 h0 = {0,0,0,0}, h1 = {0,0,0,0};
    for (; e + 1 < e1; e += 2) {
        int2 m0 = g_edges[e];
        int2 m1 = g_edges[e + 1];
        const char* p0 = ybase + (size_t)(unsigned)(m0.x & 0xFFFFFC00);
        const char* p1 = ybase + (size_t)(unsigned)(m1.x & 0xFFFFFC00);
        bool a0 = (t >= (m0.x & 15));
        bool a1 = (t >= (m1.x & 15));
        if (a0) h0 = *(const uint4*)p0;
        if (a1) h1 = *(const uint4*)p1;
        mac8(acc, h0, a0 ? __int_as_float(m0.y) : 0.f);
        mac8(acc, h1, a1 ? __int_as_float(m1.y) : 0.f);
    }
    if (e < e1) {
        int2 m0 = g_edges[e];
        const char* p0 = ybase + (size_t)(unsigned)(m0.x & 0xFFFFFC00);
        bool a0 = (t >= (m0.x & 15));
        if (a0) h0 = *(const uint4*)p0;
        mac8(acc, h0, a0 ? __int_as_float(m0.y) : 0.f);
    }
    return e1;
}

__global__ __launch_bounds__(128) void gather_kernel(const float* __restrict__ bias,
                                                     float* __restrict__ out) {
    // re-zero scan/count state for the next replay (nothing here reads it)
    {
        int b = blockIdx.x;
        if (threadIdx.x < 2) {
            int i = b * 2 + threadIdx.x;
            g_ss.counts[i] = 0;
            g_ss.cntA[i]   = 0;
        }
        if (threadIdx.x == 2 && b < NPART) g_ss.flag[b] = 0;
    }

    int gw   = (blockIdx.x * 128 + threadIdx.x) >> 5;
    int lane = threadIdx.x & 31;
    if (gw >= 2 * N_NODES) return;
    int node  = gw >> 1;
    int group = gw & 1;
    int slot  = lane >> 3;          // 0..3
    int cg    = lane & 7;           // column group (16 B)
    int t     = group * 4 + slot;

    int off = g_offsets[node];
    int mid = g_mid[node];

    unsigned long long acc[4] = {0ull, 0ull, 0ull, 0ull};
    const char* ybase = (const char*)g_y + t * 128 + cg * 16;

    if (group == 0) {
        gather_pred(off, mid, t, ybase, acc);
    } else {
        // region A: always active for t>=4 — unconditional, x4 unrolled
        int e = off;
        if ((e & 1) && e < mid) {            // align to 16B for int4 meta loads
            int2 m = g_edges[e++];
            uint4 h = *(const uint4*)(ybase + (size_t)(unsigned)(m.x & 0xFFFFFC00));
            mac8(acc, h, __int_as_float(m.y));
        }
        for (; e + 3 < mid; e += 4) {
            int4 ma = *(const int4*)&g_edges[e];       // edges e, e+1
            int4 mb = *(const int4*)&g_edges[e + 2];   // edges e+2, e+3
            uint4 h0 = *(const uint4*)(ybase + (size_t)(unsigned)(ma.x & 0xFFFFFC00));
            uint4 h1 = *(const uint4*)(ybase + (size_t)(unsigned)(ma.z & 0xFFFFFC00));
            uint4 h2 = *(const uint4*)(ybase + (size_t)(unsigned)(mb.x & 0xFFFFFC00));
            uint4 h3 = *(const uint4*)(ybase + (size_t)(unsigned)(mb.z & 0xFFFFFC00));
            mac8(acc, h0, __int_as_float(ma.y));
            mac8(acc, h1, __int_as_float(ma.w));
            mac8(acc, h2, __int_as_float(mb.y));
            mac8(acc, h3, __int_as_float(mb.w));
        }
        for (; e < mid; e++) {
            int2 m = g_edges[e];
            uint4 h = *(const uint4*)(ybase + (size_t)(unsigned)(m.x & 0xFFFFFC00));
            mac8(acc, h, __int_as_float(m.y));
        }
        // region B: tact in 4..7, predicated
        gather_pred(mid, g_offsets[node + 1], t, ybase, acc);
    }

    float4 b0 = *(const float4*)(bias + cg * 8);
    float4 b1 = *(const float4*)(bias + cg * 8 + 4);
    float2 v0 = unpack2(acc[0]);
    float2 v1 = unpack2(acc[1]);
    float2 v2 = unpack2(acc[2]);
    float2 v3 = unpack2(acc[3]);
    float* op = out + ((size_t)t * N_NODES + node) * DD + cg * 8;
    float4 o0, o1;
    o0.x = v0.x + b0.x; o0.y = v0.y + b0.y;
    o0.z = v1.x + b0.z; o0.w = v1.y + b0.w;
    o1.x = v2.x + b1.x; o1.y = v2.y + b1.y;
    o1.z = v3.x + b1.z; o1.w = v3.y + b1.w;
    *(float4*)op       = o0;
    *(float4*)(op + 4) = o1;
}

// ---------------------------------------------------------------------------
extern "C" void kernel_launch(void* const* d_in, const int* in_sizes, int n_in,
                              void* d_out, int out_size) {
    const float* x           = (const float*)d_in[0];   // [T, N, 64]
    const int*   edge_index  = (const int*)  d_in[1];   // [2, E]
    const float* edge_time   = (const float*)d_in[2];   // [E]
    const float* node_time   = (const float*)d_in[3];   // [T]
    const float* edge_weight = (const float*)d_in[4];   // [E]
    const float* W           = (const float*)d_in[5];   // [64, 64]
    const float* bias        = (const float*)d_in[6];   // [64]
    float* out = (float*)d_out;                         // [T, N, 64]

    // counts/cntA/flag start zeroed (static init) and are re-zeroed by
    // gather_kernel each run -> no memset node needed.

    // 1) y = x @ W (256 rows/block) + fused partitioned degree count
    gemm_count_kernel<<<(TOTAL_ROWS + 255) / 256, 256>>>(x, W, edge_index, edge_time, node_time);
    // 2) CSR offsets + mid + cursors
    scan_kernel<<<NPART, 256>>>();
    // 3) partitioned CSR fill (dead edges dropped)
    fill_kernel<<<(E_EDGES / 2 + 255) / 256, 256>>>(edge_index, edge_time, node_time, edge_weight);
    // 4) gather  [4th kernel -> ncu profile slot]
    gather_kernel<<<(2 * N_NODES + 3) / 4, 128>>>(bias, out);
}